// round 3
// baseline (speedup 1.0000x reference)
#include <cuda_runtime.h>
#include <math.h>

typedef unsigned long long ull;

#define Bsz 64
#define Tsz 512
#define Esz 256
#define Hsz 512
#define Vsz 128
#define Msz (Bsz*Tsz)   // 32768 rows

// ---------------- scratch (static device arrays; no runtime allocation) -------------
__device__ float g_xw[Msz*Hsz];     // input projection for current layer (t,b,h)
__device__ float g_hs0[Msz*Hsz];    // layer0 hidden states (t,b,h)
__device__ float g_hs1[Msz*Hsz];    // layer1 hidden states (t,b,h)

// ---------------- f32x2 helpers ------------------------------------------------------
__device__ __forceinline__ ull fma2(ull a, ull b, ull c){
    ull d; asm("fma.rn.f32x2 %0, %1, %2, %3;" : "=l"(d) : "l"(a), "l"(b), "l"(c)); return d;
}
__device__ __forceinline__ ull pack2(float x){
    ull d; asm("mov.b64 %0, {%1, %1};" : "=l"(d) : "f"(x)); return d;
}
__device__ __forceinline__ void unpack2(ull v, float& lo, float& hi){
    asm("mov.b64 {%0, %1}, %2;" : "=f"(lo), "=f"(hi) : "l"(v));
}

// ---------------- cluster smem helpers ----------------------------------------------
__device__ __forceinline__ unsigned smem_u32(const void* p){
    unsigned a;
    asm("{ .reg .u64 t; cvta.to.shared.u64 t, %1; cvt.u32.u64 %0, t; }" : "=r"(a) : "l"(p));
    return a;
}
__device__ __forceinline__ unsigned mapa_rank(unsigned laddr, unsigned r){
    unsigned ra; asm("mapa.shared::cluster.u32 %0, %1, %2;" : "=r"(ra) : "r"(laddr), "r"(r));
    return ra;
}
__device__ __forceinline__ void sts_remote(unsigned addr, float v){
    asm volatile("st.shared::cluster.f32 [%0], %1;" :: "r"(addr), "f"(v) : "memory");
}
__device__ __forceinline__ void cluster_bar(){
    asm volatile("barrier.cluster.arrive.aligned;" ::: "memory");
    asm volatile("barrier.cluster.wait.aligned;"   ::: "memory");
}

// ---------------- kernel: fp32 GEMM  C[M,N] = A[M,K] @ W[N,K]^T + bias --------------
// mode 0: C row-major by A-row.
// mode 1: A-row=(t*B+b) remapped to out[(b*T+t)*N+n] (logits)
// mode 2: A-row gathered through embedding: A[m][k] = emb[x[b*T+t]][k]  (K=Esz)
__global__ void __launch_bounds__(256) k_gemm(const float* __restrict__ A,
                                              const float* __restrict__ W,
                                              const float* __restrict__ bias,
                                              float* __restrict__ C,
                                              int M, int N, int K, int mode,
                                              const int* __restrict__ xidx){
    __shared__ __align__(16) float As[128*20];   // [m][k], row stride 20 (pad)
    __shared__ __align__(16) float Bs[16*130];   // [k][n], row stride 130 (pad)
    const int tid = threadIdx.x;
    const int m0 = blockIdx.x*128;
    const int n0 = blockIdx.y*128;
    const int tx = tid & 15;       // n-group (8 n each)
    const int ty = tid >> 4;       // m-group (8 m each)
    const int mlA = tid >> 2, qA = tid & 3;
    const int nnB = tid & 127, hfB = tid >> 7;

    ull acc[8][4];
#pragma unroll
    for (int i=0;i<8;i++)
#pragma unroll
        for (int j=0;j<4;j++) acc[i][j] = 0ull;

    for (int k0=0;k0<K;k0+=16){
        __syncthreads();
        // A tile: 128x16
#pragma unroll
        for (int p=0;p<2;p++){
            int m = mlA + p*64;
            int row = m0 + m;
            const float* ap;
            if (mode == 2){
                int b = row & 63; int tt = row >> 6;
                int v = xidx[b*Tsz + tt];
                ap = &A[(size_t)v*Esz + k0 + qA*4];
            } else {
                ap = &A[(size_t)row*K + k0 + qA*4];
            }
            float4 va = *(const float4*)ap;
            *(float4*)&As[m*20 + qA*4] = va;
        }
        // B tile: W[n][k] -> Bs[k][n]
        {
            const float* wp = &W[(size_t)(n0+nnB)*K + k0 + hfB*8];
            float4 v0 = *(const float4*)wp;
            float4 v1 = *(const float4*)(wp+4);
            int kb = hfB*8;
            Bs[(kb+0)*130+nnB]=v0.x; Bs[(kb+1)*130+nnB]=v0.y;
            Bs[(kb+2)*130+nnB]=v0.z; Bs[(kb+3)*130+nnB]=v0.w;
            Bs[(kb+4)*130+nnB]=v1.x; Bs[(kb+5)*130+nnB]=v1.y;
            Bs[(kb+6)*130+nnB]=v1.z; Bs[(kb+7)*130+nnB]=v1.w;
        }
        __syncthreads();
#pragma unroll
        for (int kk=0;kk<16;kk++){
            int k = (kk + tx) & 15;                 // per-lane k rotation: kills bank conflicts
            const ull* bp = (const ull*)&Bs[k*130 + tx*8];
            ull b0=bp[0], b1=bp[1], b2v=bp[2], b3=bp[3];
#pragma unroll
            for (int i=0;i<8;i++){
                ull a2 = pack2(As[(ty*8+i)*20 + k]);
                acc[i][0] = fma2(a2, b0,  acc[i][0]);
                acc[i][1] = fma2(a2, b1,  acc[i][1]);
                acc[i][2] = fma2(a2, b2v, acc[i][2]);
                acc[i][3] = fma2(a2, b3,  acc[i][3]);
            }
        }
    }
    // epilogue: + bias, write (with optional logits remap)
#pragma unroll
    for (int i=0;i<8;i++){
        int row = m0 + ty*8 + i;
        size_t obase;
        if (mode == 1){ int b = row & 63; int tt = row >> 6; obase = ((size_t)b*Tsz + tt)*(size_t)N; }
        else obase = (size_t)row * (size_t)N;
#pragma unroll
        for (int jn=0;jn<4;jn++){
            int n = n0 + tx*8 + jn*2;
            float2 bv = *(const float2*)&bias[n];
            float lo, hi; unpack2(acc[i][jn], lo, hi);
            float2 o; o.x = lo + bv.x; o.y = hi + bv.y;
            *(float2*)&C[obase + n] = o;
        }
    }
}

// ---------------- kernel: cluster-based persistent recurrence ------------------------
// 128 CTAs = 16 clusters x 8 CTAs. Cluster cl owns batches [cl*4, cl*4+4).
// CTA rank owns j in [rank*64, rank*64+64). Thread (warp w, lane): j = rank*64+w*8+(lane>>2),
// k-quarter kq = lane&3 (128 k each). Weights W_hh[j][kq*128..+128) live in 64 f32x2 regs.
// Hidden state for the cluster's 4 batches lives in each CTA's smem (ping-pong buffers),
// refreshed every step by DSMEM remote stores + one cluster barrier. No grid sync at all.
#define CHUNK 132                     // 128 floats + 4 pad (bank de-conflict)
#define BUFF  (16*CHUNK)              // 4 batches x 4 k-quarters

__global__ void __launch_bounds__(256,1) __cluster_dims__(8,1,1)
k_rnn(const float* __restrict__ xw, float* __restrict__ hs,
      const float* __restrict__ Whh, float* __restrict__ hlast){
    __shared__ __align__(16) float sh[2*BUFF];
    const int cl   = blockIdx.x >> 3;
    const int rank = blockIdx.x & 7;
    const int tid  = threadIdx.x;
    const int w    = tid >> 5;
    const int lane = tid & 31;
    const int jl   = lane >> 2;
    const int kq   = lane & 3;
    const int j     = rank*64 + w*8 + jl;
    const int bglob = cl*4 + kq;          // this thread's output batch

    // ---- load weights: W_hh[j][kq*128 .. kq*128+128) as 64 f32x2 ----
    ull w2[64];
    const ull* wp = (const ull*)(Whh + (size_t)j*Hsz + kq*128);
#pragma unroll
    for (int i=0;i<64;i++) w2[i] = wp[i];

    // ---- precompute DSMEM addresses ----
    const unsigned sbase = smem_u32(sh);
    unsigned ra[8];
#pragma unroll
    for (int r=0;r<8;r++) ra[r] = mapa_rank(sbase, r);
    // my output value is h[b=kq][k=j] for consumers: chunk = kq*4 + (j>>7), pos = j&127
    const unsigned woff0 = (unsigned)(((kq*4 + (j>>7))*CHUNK + (j&127))*4);
    const unsigned woff1 = woff0 + BUFF*4;

    // ---- t = 0: h_prev = 0 ----
    {
        float z  = xw[(size_t)bglob*Hsz + j];
        float hv = tanhf(z);
        hs[(size_t)bglob*Hsz + j] = hv;
#pragma unroll
        for (int r=0;r<8;r++) sts_remote(ra[r] + woff0, hv);
    }
    cluster_bar();

    for (int t=1;t<Tsz;t++){
        // prefetch xw early (L2 latency overlaps the fma loop)
        float xwv = xw[((size_t)t*Bsz + bglob)*Hsz + j];

        const float* bufr = sh + ((t-1)&1)*BUFF;
        const ull* h0 = (const ull*)(bufr + (0*4+kq)*CHUNK);
        const ull* h1 = (const ull*)(bufr + (1*4+kq)*CHUNK);
        const ull* h2 = (const ull*)(bufr + (2*4+kq)*CHUNK);
        const ull* h3 = (const ull*)(bufr + (3*4+kq)*CHUNK);
        ull a0=0ull, a1=0ull, a2=0ull, a3=0ull;
#pragma unroll
        for (int i=0;i<64;i+=2){
            ulonglong2 p0 = *(const ulonglong2*)&h0[i];
            ulonglong2 p1 = *(const ulonglong2*)&h1[i];
            ulonglong2 p2 = *(const ulonglong2*)&h2[i];
            ulonglong2 p3 = *(const ulonglong2*)&h3[i];
            a0 = fma2(p0.x, w2[i], a0);  a0 = fma2(p0.y, w2[i+1], a0);
            a1 = fma2(p1.x, w2[i], a1);  a1 = fma2(p1.y, w2[i+1], a1);
            a2 = fma2(p2.x, w2[i], a2);  a2 = fma2(p2.y, w2[i+1], a2);
            a3 = fma2(p3.x, w2[i], a3);  a3 = fma2(p3.y, w2[i+1], a3);
        }
        float l, h;
        unpack2(a0,l,h); float z0 = l+h;
        unpack2(a1,l,h); float z1 = l+h;
        unpack2(a2,l,h); float z2 = l+h;
        unpack2(a3,l,h); float z3 = l+h;
        // reduce over the 4 k-quarter lanes (lane bits 0..1)
        z0 += __shfl_xor_sync(0xffffffffu, z0, 1); z0 += __shfl_xor_sync(0xffffffffu, z0, 2);
        z1 += __shfl_xor_sync(0xffffffffu, z1, 1); z1 += __shfl_xor_sync(0xffffffffu, z1, 2);
        z2 += __shfl_xor_sync(0xffffffffu, z2, 1); z2 += __shfl_xor_sync(0xffffffffu, z2, 2);
        z3 += __shfl_xor_sync(0xffffffffu, z3, 1); z3 += __shfl_xor_sync(0xffffffffu, z3, 2);
        float rsel = (kq==0) ? z0 : (kq==1) ? z1 : (kq==2) ? z2 : z3;

        float hv = tanhf(rsel + xwv);
        hs[((size_t)t*Bsz + bglob)*Hsz + j] = hv;
        if (t == Tsz-1) hlast[(size_t)bglob*Hsz + j] = hv;

        unsigned woff = (t&1) ? woff1 : woff0;
#pragma unroll
        for (int r=0;r<8;r++) sts_remote(ra[r] + woff, hv);
        cluster_bar();
    }
}

// ---------------- launch -------------------------------------------------------------
extern "C" void kernel_launch(void* const* d_in, const int* in_sizes, int n_in,
                              void* d_out, int out_size){
    const int*   x    = (const int*)  d_in[0];
    const float* emb  = (const float*)d_in[1];
    const float* Wxh0 = (const float*)d_in[2];
    const float* Whh0 = (const float*)d_in[3];
    const float* bh0  = (const float*)d_in[4];
    const float* Wxh1 = (const float*)d_in[5];
    const float* Whh1 = (const float*)d_in[6];
    const float* bh1  = (const float*)d_in[7];
    const float* Why  = (const float*)d_in[8];
    const float* by   = (const float*)d_in[9];
    float* out = (float*)d_out;

    float *xwbuf, *hs0, *hs1;
    cudaGetSymbolAddress((void**)&xwbuf, g_xw);
    cudaGetSymbolAddress((void**)&hs0,   g_hs0);
    cudaGetSymbolAddress((void**)&hs1,   g_hs1);

    const size_t LOGITS = (size_t)Bsz*Tsz*Vsz;   // 4194304

    dim3 gH(Msz/128, Hsz/128);

    // 1) xw0 = gather(emb, x) @ Wxh0^T + bh0   (gather fused into A-load)
    k_gemm<<<gH, 256>>>(emb, Wxh0, bh0, xwbuf, Msz, Hsz, Esz, 2, x);

    // 2) layer-0 recurrence -> hs0, h_last0
    k_rnn<<<128, 256>>>(xwbuf, hs0, Whh0, out + LOGITS);

    // 3) xw1 = hs0 @ Wxh1^T + bh1
    k_gemm<<<gH, 256>>>(hs0, Wxh1, bh1, xwbuf, Msz, Hsz, Hsz, 0, 0);

    // 4) layer-1 recurrence -> hs1, h_last1
    k_rnn<<<128, 256>>>(xwbuf, hs1, Whh1, out + LOGITS + (size_t)Bsz*Hsz);

    // 5) logits = hs1 @ Why^T + by  (remapped to (b,t,v))
    dim3 gV(Msz/128, Vsz/128);
    k_gemm<<<gV, 256>>>(hs1, Why, by, out, Msz, Vsz, Hsz, 1, 0);
}

// round 5
// speedup vs baseline: 1.5887x; 1.5887x over previous
#include <cuda_runtime.h>
#include <math.h>

typedef unsigned long long ull;

#define Bsz 64
#define Tsz 512
#define Esz 256
#define Hsz 512
#define Vsz 128
#define Msz (Bsz*Tsz)   // 32768 rows

// ---------------- scratch (static device arrays; no runtime allocation) -------------
__device__ float g_xw[Msz*Hsz];     // input projection for current layer (t,b,h)
__device__ float g_hs0[Msz*Hsz];    // layer0 hidden states (t,b,h)
__device__ float g_hs1[Msz*Hsz];    // layer1 hidden states (t,b,h)

// ---------------- f32x2 helpers ------------------------------------------------------
__device__ __forceinline__ ull fma2(ull a, ull b, ull c){
    ull d; asm("fma.rn.f32x2 %0, %1, %2, %3;" : "=l"(d) : "l"(a), "l"(b), "l"(c)); return d;
}
__device__ __forceinline__ ull pack2(float x){
    ull d; asm("mov.b64 %0, {%1, %1};" : "=l"(d) : "f"(x)); return d;
}
__device__ __forceinline__ void unpack2(ull v, float& lo, float& hi){
    asm("mov.b64 {%0, %1}, %2;" : "=f"(lo), "=f"(hi) : "l"(v));
}

// ---------------- cluster smem helpers ----------------------------------------------
__device__ __forceinline__ unsigned smem_u32(const void* p){
    unsigned a;
    asm("{ .reg .u64 t; cvta.to.shared.u64 t, %1; cvt.u32.u64 %0, t; }" : "=r"(a) : "l"(p));
    return a;
}
__device__ __forceinline__ unsigned mapa_rank(unsigned laddr, unsigned r){
    unsigned ra; asm("mapa.shared::cluster.u32 %0, %1, %2;" : "=r"(ra) : "r"(laddr), "r"(r));
    return ra;
}
__device__ __forceinline__ void sts_remote(unsigned addr, float v){
    asm volatile("st.shared::cluster.f32 [%0], %1;" :: "r"(addr), "f"(v) : "memory");
}
__device__ __forceinline__ void cluster_arrive(){
    asm volatile("barrier.cluster.arrive.aligned;" ::: "memory");
}
__device__ __forceinline__ void cluster_wait(){
    asm volatile("barrier.cluster.wait.aligned;"   ::: "memory");
}

// ---------------- kernel: fp32 GEMM  C[M,N] = A[M,K] @ W[N,K]^T + bias --------------
// mode 0: C row-major by A-row.
// mode 1: A-row=(t*B+b) remapped to out[(b*T+t)*N+n] (logits)
// mode 2: A-row gathered through embedding: A[m][k] = emb[x[b*T+t]][k]  (K=Esz)
__global__ void __launch_bounds__(256) k_gemm(const float* __restrict__ A,
                                              const float* __restrict__ W,
                                              const float* __restrict__ bias,
                                              float* __restrict__ C,
                                              int M, int N, int K, int mode,
                                              const int* __restrict__ xidx){
    __shared__ __align__(16) float As[128*20];   // [m][k], row stride 20 (pad)
    __shared__ __align__(16) float Bs[16*130];   // [k][n], row stride 130 (pad)
    const int tid = threadIdx.x;
    const int m0 = blockIdx.x*128;
    const int n0 = blockIdx.y*128;
    const int tx = tid & 15;       // n-group (8 n each)
    const int ty = tid >> 4;       // m-group (8 m each)
    const int mlA = tid >> 2, qA = tid & 3;
    const int nnB = tid & 127, hfB = tid >> 7;

    ull acc[8][4];
#pragma unroll
    for (int i=0;i<8;i++)
#pragma unroll
        for (int j=0;j<4;j++) acc[i][j] = 0ull;

    for (int k0=0;k0<K;k0+=16){
        __syncthreads();
        // A tile: 128x16
#pragma unroll
        for (int p=0;p<2;p++){
            int m = mlA + p*64;
            int row = m0 + m;
            const float* ap;
            if (mode == 2){
                int b = row & 63; int tt = row >> 6;
                int v = xidx[b*Tsz + tt];
                ap = &A[(size_t)v*Esz + k0 + qA*4];
            } else {
                ap = &A[(size_t)row*K + k0 + qA*4];
            }
            float4 va = *(const float4*)ap;
            *(float4*)&As[m*20 + qA*4] = va;
        }
        // B tile: W[n][k] -> Bs[k][n]
        {
            const float* wp = &W[(size_t)(n0+nnB)*K + k0 + hfB*8];
            float4 v0 = *(const float4*)wp;
            float4 v1 = *(const float4*)(wp+4);
            int kb = hfB*8;
            Bs[(kb+0)*130+nnB]=v0.x; Bs[(kb+1)*130+nnB]=v0.y;
            Bs[(kb+2)*130+nnB]=v0.z; Bs[(kb+3)*130+nnB]=v0.w;
            Bs[(kb+4)*130+nnB]=v1.x; Bs[(kb+5)*130+nnB]=v1.y;
            Bs[(kb+6)*130+nnB]=v1.z; Bs[(kb+7)*130+nnB]=v1.w;
        }
        __syncthreads();
#pragma unroll
        for (int kk=0;kk<16;kk++){
            int k = (kk + tx) & 15;                 // per-lane k rotation: kills bank conflicts
            const ull* bp = (const ull*)&Bs[k*130 + tx*8];
            ull b0=bp[0], b1=bp[1], b2v=bp[2], b3=bp[3];
#pragma unroll
            for (int i=0;i<8;i++){
                ull a2 = pack2(As[(ty*8+i)*20 + k]);
                acc[i][0] = fma2(a2, b0,  acc[i][0]);
                acc[i][1] = fma2(a2, b1,  acc[i][1]);
                acc[i][2] = fma2(a2, b2v, acc[i][2]);
                acc[i][3] = fma2(a2, b3,  acc[i][3]);
            }
        }
    }
    // epilogue: + bias, write (with optional logits remap)
#pragma unroll
    for (int i=0;i<8;i++){
        int row = m0 + ty*8 + i;
        size_t obase;
        if (mode == 1){ int b = row & 63; int tt = row >> 6; obase = ((size_t)b*Tsz + tt)*(size_t)N; }
        else obase = (size_t)row * (size_t)N;
#pragma unroll
        for (int jn=0;jn<4;jn++){
            int n = n0 + tx*8 + jn*2;
            float2 bv = *(const float2*)&bias[n];
            float lo, hi; unpack2(acc[i][jn], lo, hi);
            float2 o; o.x = lo + bv.x; o.y = hi + bv.y;
            *(float2*)&C[obase + n] = o;
        }
    }
}

// ---------------- kernel: cluster-based persistent recurrence ------------------------
// 128 CTAs = 16 clusters x 8 CTAs. Cluster cl owns batches [cl*4, cl*4+4).
// CTA rank owns j in [rank*64, rank*64+64).
// Thread tile: jn=4 j, bn=4 batches, kn=32 k.
//   warp w (8/CTA), lane = jq(1b)<<4 | kq(4b):
//     j0 = rank*64 + w*8 + jq*4; k range = kq*32 .. +32
// Weights: 4 j x 16 f32x2 = 64 ull in regs. h reads: 4 b x 32 k = 512B/thread/step.
// Hidden state in smem chunks of 32 floats + 4 pad (stride 36).
// 16-lane select-based butterfly reduce (static reg indices, 15 shuffles) ->
// one output/thread -> DSMEM push x8 -> cluster barrier (kept on EVERY step,
// including the last: remote stores must land before any CTA exits).
#define CHUNK36 36
#define BUFSZ  (4*16*CHUNK36)      // 4 batches x 16 chunks x 36 floats = 2304

__global__ void __launch_bounds__(256,1) __cluster_dims__(8,1,1)
k_rnn(const float* __restrict__ xw, float* __restrict__ hs,
      const float* __restrict__ Whh, float* __restrict__ hlast){
    __shared__ __align__(16) float sh[2*BUFSZ];
    const int cl   = blockIdx.x >> 3;
    const int rank = blockIdx.x & 7;
    const int tid  = threadIdx.x;
    const int w    = tid >> 5;
    const int lane = tid & 31;
    const int kq   = lane & 15;          // k-slice (32 k)
    const int jq   = lane >> 4;          // j-quad within warp
    const int j0   = rank*64 + w*8 + jq*4;
    // this thread's final output after reduce: o = kq -> (b_out, jj_out)
    const int b_out = kq >> 2;
    const int j_out = j0 + (kq & 3);
    const int bglob = cl*4 + b_out;

    // ---- load weights: W_hh[j0+jj][kq*32 .. +32) as 16 f32x2 each ----
    ull w2[4][16];
#pragma unroll
    for (int jj=0;jj<4;jj++){
        const ull* wp = (const ull*)(Whh + (size_t)(j0+jj)*Hsz + kq*32);
#pragma unroll
        for (int i=0;i<16;i++) w2[jj][i] = wp[i];
    }

    // ---- DSMEM addresses ----
    const unsigned sbase = smem_u32(sh);
    unsigned ra[8];
#pragma unroll
    for (int r=0;r<8;r++) ra[r] = mapa_rank(sbase, r);
    // consumers index h[b][k] at ((b*16 + (k>>5))*36 + (k&31)); our k = j_out
    const unsigned woff0 = (unsigned)(((b_out*16 + (j_out>>5))*CHUNK36 + (j_out&31))*4);
    const unsigned woff1 = woff0 + BUFSZ*4;

    // ---- t = 0: h_prev = 0 ----
    {
        float z  = xw[(size_t)bglob*Hsz + j_out];
        float hv = tanhf(z);
        hs[(size_t)bglob*Hsz + j_out] = hv;
#pragma unroll
        for (int r=0;r<8;r++) sts_remote(ra[r] + woff0, hv);
    }
    cluster_arrive();
    float xwv = xw[((size_t)1*Bsz + bglob)*Hsz + j_out];
    cluster_wait();

    const bool hi8 = (lane & 8) != 0;
    const bool hi4 = (lane & 4) != 0;
    const bool hi2 = (lane & 2) != 0;
    const bool hi1 = (lane & 1) != 0;

    for (int t=1;t<Tsz;t++){
        const float* bufr = sh + ((t-1)&1)*BUFSZ;
        ull acc[4][4];
#pragma unroll
        for (int b=0;b<4;b++)
#pragma unroll
            for (int jj=0;jj<4;jj++) acc[b][jj] = 0ull;

#pragma unroll
        for (int b=0;b<4;b++){
            const ull* hq = (const ull*)(bufr + (b*16 + kq)*CHUNK36);
#pragma unroll
            for (int kk=0;kk<16;kk+=2){
                ulonglong2 p = *(const ulonglong2*)&hq[kk];
#pragma unroll
                for (int jj=0;jj<4;jj++){
                    acc[b][jj] = fma2(p.x, w2[jj][kk],   acc[b][jj]);
                    acc[b][jj] = fma2(p.y, w2[jj][kk+1], acc[b][jj]);
                }
            }
        }
        // collapse f32x2 -> 16 scalars v[o], o = b*4 + jj
        float v[16];
#pragma unroll
        for (int b=0;b<4;b++)
#pragma unroll
            for (int jj=0;jj<4;jj++){
                float l, h; unpack2(acc[b][jj], l, h);
                v[b*4+jj] = l + h;
            }
        // 16-lane butterfly over kq bits, select-based (all indices compile-time):
        // after folding bit m, v[o] holds output o + (lane & folded_mask).
#pragma unroll
        for (int o=0;o<8;o++){
            float keepv = hi8 ? v[o+8] : v[o];
            float sendv = hi8 ? v[o]   : v[o+8];
            v[o] = keepv + __shfl_xor_sync(0xffffffffu, sendv, 8);
        }
#pragma unroll
        for (int o=0;o<4;o++){
            float keepv = hi4 ? v[o+4] : v[o];
            float sendv = hi4 ? v[o]   : v[o+4];
            v[o] = keepv + __shfl_xor_sync(0xffffffffu, sendv, 4);
        }
#pragma unroll
        for (int o=0;o<2;o++){
            float keepv = hi2 ? v[o+2] : v[o];
            float sendv = hi2 ? v[o]   : v[o+2];
            v[o] = keepv + __shfl_xor_sync(0xffffffffu, sendv, 2);
        }
        {
            float keepv = hi1 ? v[1] : v[0];
            float sendv = hi1 ? v[0] : v[1];
            v[0] = keepv + __shfl_xor_sync(0xffffffffu, sendv, 1);
        }

        float hv = tanhf(v[0] + xwv);
        hs[((size_t)t*Bsz + bglob)*Hsz + j_out] = hv;

        unsigned woff = (t&1) ? woff1 : woff0;
#pragma unroll
        for (int r=0;r<8;r++) sts_remote(ra[r] + woff, hv);

        cluster_arrive();
        if (t == Tsz-1){
            hlast[(size_t)bglob*Hsz + j_out] = hv;   // hidden inside barrier window
        } else {
            xwv = xw[((size_t)(t+1)*Bsz + bglob)*Hsz + j_out];  // overlap with wait
        }
        cluster_wait();   // also guarantees peers' remote stores landed before exit
    }
}

// ---------------- launch -------------------------------------------------------------
extern "C" void kernel_launch(void* const* d_in, const int* in_sizes, int n_in,
                              void* d_out, int out_size){
    const int*   x    = (const int*)  d_in[0];
    const float* emb  = (const float*)d_in[1];
    const float* Wxh0 = (const float*)d_in[2];
    const float* Whh0 = (const float*)d_in[3];
    const float* bh0  = (const float*)d_in[4];
    const float* Wxh1 = (const float*)d_in[5];
    const float* Whh1 = (const float*)d_in[6];
    const float* bh1  = (const float*)d_in[7];
    const float* Why  = (const float*)d_in[8];
    const float* by   = (const float*)d_in[9];
    float* out = (float*)d_out;

    float *xwbuf, *hs0, *hs1;
    cudaGetSymbolAddress((void**)&xwbuf, g_xw);
    cudaGetSymbolAddress((void**)&hs0,   g_hs0);
    cudaGetSymbolAddress((void**)&hs1,   g_hs1);

    const size_t LOGITS = (size_t)Bsz*Tsz*Vsz;   // 4194304

    dim3 gH(Msz/128, Hsz/128);

    // 1) xw0 = gather(emb, x) @ Wxh0^T + bh0   (gather fused into A-load)
    k_gemm<<<gH, 256>>>(emb, Wxh0, bh0, xwbuf, Msz, Hsz, Esz, 2, x);

    // 2) layer-0 recurrence -> hs0, h_last0
    k_rnn<<<128, 256>>>(xwbuf, hs0, Whh0, out + LOGITS);

    // 3) xw1 = hs0 @ Wxh1^T + bh1
    k_gemm<<<gH, 256>>>(hs0, Wxh1, bh1, xwbuf, Msz, Hsz, Hsz, 0, 0);

    // 4) layer-1 recurrence -> hs1, h_last1
    k_rnn<<<128, 256>>>(xwbuf, hs1, Whh1, out + LOGITS + (size_t)Bsz*Hsz);

    // 5) logits = hs1 @ Why^T + by  (remapped to (b,t,v))
    dim3 gV(Msz/128, Vsz/128);
    k_gemm<<<gV, 256>>>(hs1, Why, by, out, Msz, Vsz, Hsz, 1, 0);
}